// round 6
// baseline (speedup 1.0000x reference)
#include <cuda_runtime.h>
#include <cstdint>

// ---------------- problem constants ----------------
constexpr int NN  = 38000;   // nodes
constexpr int IND = 64;      // input dim
constexpr int HID = 128;
constexpr int RR  = 8;       // relations
constexpr int EE  = 200000;  // edges per relation
constexpr int NR  = 60000;   // rows
constexpr int FF  = 19;      // features per row
constexpr int NC  = 10;      // classes

// ---------------- device scratch (static, no allocation) ----------------
__device__ float g_h0[(size_t)NN * HID];
__device__ float g_h1[(size_t)NN * HID];
__device__ float g_h2[(size_t)NN * HID];
__device__ float g_agg[(size_t)RR * NN * HID];      // 155.6 MB
__device__ float g_deg_out[RR * NN];
__device__ float g_deg_in[RR * NN];
__device__ float g_norm_s[RR * NN];
__device__ float g_norm_d[RR * NN];
__device__ float g_mean[(size_t)NR * HID];
__device__ float g_x1[(size_t)NR * HID];
__device__ float g_x2[(size_t)NR * HID];
__device__ int   g_mask_is_int;

// ---------------- zero ----------------
__global__ void k_zero4(float4* p, long long n4) {
    long long i = (long long)blockIdx.x * blockDim.x + threadIdx.x;
    long long stride = (long long)gridDim.x * blockDim.x;
    float4 z = make_float4(0.f, 0.f, 0.f, 0.f);
    for (; i < n4; i += stride) p[i] = z;
}

// ---------------- mask dtype detection ----------------
// Reference row_mask is bool; the harness canonicalizes dtypes (f32/i32/bf16),
// so it is most likely int32 — but detect instead of guessing. Random 0/1
// bytes -> ~50% nonzero; 0/1 int32 viewed as bytes -> ~12.5% nonzero.
__global__ void k_detect_mask(const unsigned char* __restrict__ m) {
    __shared__ int cnt;
    if (threadIdx.x == 0) cnt = 0;
    __syncthreads();
    int local = 0;
    for (int i = threadIdx.x; i < 65536; i += blockDim.x)
        local += (m[i] != 0);
    atomicAdd(&cnt, local);
    __syncthreads();
    if (threadIdx.x == 0) g_mask_is_int = (cnt < 16384) ? 1 : 0;
}

// ---------------- degrees ----------------
__global__ void k_deg(const int* __restrict__ src, const int* __restrict__ dst) {
    long long i = (long long)blockIdx.x * blockDim.x + threadIdx.x;
    if (i >= (long long)RR * EE) return;
    int r = (int)(i / EE);
    atomicAdd(&g_deg_out[r * NN + src[i]], 1.f);
    atomicAdd(&g_deg_in [r * NN + dst[i]], 1.f);
}

__global__ void k_norms() {
    int i = blockIdx.x * blockDim.x + threadIdx.x;
    if (i >= RR * NN) return;
    g_norm_s[i] = rsqrtf(fmaxf(g_deg_out[i], 1.f));
    g_norm_d[i] = rsqrtf(fmaxf(g_deg_in [i], 1.f));
}

// ---------------- edge aggregation: one warp per edge, float4 RED ----------------
__global__ void k_agg(const float* __restrict__ h,
                      const int* __restrict__ src, const int* __restrict__ dst) {
    long long gtid = (long long)blockIdx.x * blockDim.x + threadIdx.x;
    long long w = gtid >> 5;
    if (w >= (long long)RR * EE) return;
    int lane = threadIdx.x & 31;
    int r = (int)(w / EE);
    int s = __ldg(&src[w]);
    int d = __ldg(&dst[w]);
    float sc = __ldg(&g_norm_s[(size_t)r * NN + s]);
    float4 v = __ldg((const float4*)(h + (size_t)s * HID) + lane);
    v.x *= sc; v.y *= sc; v.z *= sc; v.w *= sc;
    atomicAdd((float4*)(g_agg + ((size_t)r * NN + d) * HID) + lane, v);
}

// ---------------- generic tiled fp32 GEMM: C[M][128] = act(A[M][K] @ B[K][128] + bias) ----
// BM=64, BN=128, BK=16, 256 threads, each thread 8x4 outputs.
template <bool RELU>
__global__ void k_gemm(const float* __restrict__ A, const float* __restrict__ B,
                       const float* __restrict__ bias, float* __restrict__ C,
                       int M, int K) {
    __shared__ float As[16][68];   // [k][m], row stride 272B (16B multiple)
    __shared__ float Bs[16][128];
    const int tid = threadIdx.x;
    const int col_t = tid & 31;   // 32 col groups * 4
    const int row_t = tid >> 5;   // 8 row groups * 8
    const int m0 = blockIdx.x * 64;

    float acc[8][4];
#pragma unroll
    for (int i = 0; i < 8; i++)
#pragma unroll
        for (int j = 0; j < 4; j++) acc[i][j] = 0.f;

    const int a_m  = tid >> 2;        // 0..63
    const int a_kq = tid & 3;         // 0..3
    const int b_k  = tid >> 5;        // 0..7
    const int b_j  = (tid & 31) * 4;

    for (int k0 = 0; k0 < K; k0 += 16) {
        float4 av = make_float4(0.f, 0.f, 0.f, 0.f);
        int arow = m0 + a_m;
        if (arow < M)
            av = *(const float4*)(A + (size_t)arow * K + k0 + a_kq * 4);
        As[a_kq * 4 + 0][a_m] = av.x;
        As[a_kq * 4 + 1][a_m] = av.y;
        As[a_kq * 4 + 2][a_m] = av.z;
        As[a_kq * 4 + 3][a_m] = av.w;
        *(float4*)&Bs[b_k    ][b_j] = *(const float4*)(B + (size_t)(k0 + b_k    ) * HID + b_j);
        *(float4*)&Bs[b_k + 8][b_j] = *(const float4*)(B + (size_t)(k0 + b_k + 8) * HID + b_j);
        __syncthreads();
#pragma unroll
        for (int k = 0; k < 16; k++) {
            float4 a0 = *(float4*)&As[k][row_t * 8];
            float4 a1 = *(float4*)&As[k][row_t * 8 + 4];
            float4 bv = *(float4*)&Bs[k][col_t * 4];
            float ar[8] = {a0.x, a0.y, a0.z, a0.w, a1.x, a1.y, a1.z, a1.w};
            float br[4] = {bv.x, bv.y, bv.z, bv.w};
#pragma unroll
            for (int i = 0; i < 8; i++)
#pragma unroll
                for (int j = 0; j < 4; j++) acc[i][j] += ar[i] * br[j];
        }
        __syncthreads();
    }

    float bj[4];
#pragma unroll
    for (int j = 0; j < 4; j++) bj[j] = bias[col_t * 4 + j];
#pragma unroll
    for (int i = 0; i < 8; i++) {
        int row = m0 + row_t * 8 + i;
        if (row < M) {
            float4 o;
            o.x = acc[i][0] + bj[0];
            o.y = acc[i][1] + bj[1];
            o.z = acc[i][2] + bj[2];
            o.w = acc[i][3] + bj[3];
            if (RELU) {
                o.x = fmaxf(o.x, 0.f); o.y = fmaxf(o.y, 0.f);
                o.z = fmaxf(o.z, 0.f); o.w = fmaxf(o.w, 0.f);
            }
            *(float4*)(C + (size_t)row * HID + col_t * 4) = o;
        }
    }
}

// ---------------- RGCN layer GEMM: out[N][128] = act( sum_r (agg_r * norm_d_r) @ W[r] + sum_r b[r] )
// Implicit A = [NN][R*128] with per-(r,row) scale; K = R*128 = 1024.
template <bool RELU>
__global__ void k_layer_gemm(const float* __restrict__ W,   // [R][128][128]
                             const float* __restrict__ b,   // [R][128]
                             float* __restrict__ out) {
    __shared__ float As[16][68];
    __shared__ float Bs[16][128];
    const int tid = threadIdx.x;
    const int col_t = tid & 31;
    const int row_t = tid >> 5;
    const int m0 = blockIdx.x * 64;

    float acc[8][4];
#pragma unroll
    for (int i = 0; i < 8; i++)
#pragma unroll
        for (int j = 0; j < 4; j++) acc[i][j] = 0.f;

    const int a_m  = tid >> 2;
    const int a_kq = tid & 3;
    const int b_k  = tid >> 5;
    const int b_j  = (tid & 31) * 4;

    for (int k0 = 0; k0 < RR * HID; k0 += 16) {
        const int r  = k0 >> 7;        // constant across the BK=16 tile
        const int kl = k0 & 127;
        float4 av = make_float4(0.f, 0.f, 0.f, 0.f);
        int arow = m0 + a_m;
        if (arow < NN) {
            float nd = __ldg(&g_norm_d[(size_t)r * NN + arow]);
            av = *(const float4*)(g_agg + ((size_t)r * NN + arow) * HID + kl + a_kq * 4);
            av.x *= nd; av.y *= nd; av.z *= nd; av.w *= nd;
        }
        As[a_kq * 4 + 0][a_m] = av.x;
        As[a_kq * 4 + 1][a_m] = av.y;
        As[a_kq * 4 + 2][a_m] = av.z;
        As[a_kq * 4 + 3][a_m] = av.w;
        *(float4*)&Bs[b_k    ][b_j] = *(const float4*)(W + (size_t)(k0 + b_k    ) * HID + b_j);
        *(float4*)&Bs[b_k + 8][b_j] = *(const float4*)(W + (size_t)(k0 + b_k + 8) * HID + b_j);
        __syncthreads();
#pragma unroll
        for (int k = 0; k < 16; k++) {
            float4 a0 = *(float4*)&As[k][row_t * 8];
            float4 a1 = *(float4*)&As[k][row_t * 8 + 4];
            float4 bv = *(float4*)&Bs[k][col_t * 4];
            float ar[8] = {a0.x, a0.y, a0.z, a0.w, a1.x, a1.y, a1.z, a1.w};
            float br[4] = {bv.x, bv.y, bv.z, bv.w};
#pragma unroll
            for (int i = 0; i < 8; i++)
#pragma unroll
                for (int j = 0; j < 4; j++) acc[i][j] += ar[i] * br[j];
        }
        __syncthreads();
    }

    float bj[4];
#pragma unroll
    for (int j = 0; j < 4; j++) {
        float s = 0.f;
#pragma unroll
        for (int r = 0; r < RR; r++) s += b[r * HID + col_t * 4 + j];
        bj[j] = s;
    }
#pragma unroll
    for (int i = 0; i < 8; i++) {
        int row = m0 + row_t * 8 + i;
        if (row < NN) {
            float4 o;
            o.x = acc[i][0] + bj[0];
            o.y = acc[i][1] + bj[1];
            o.z = acc[i][2] + bj[2];
            o.w = acc[i][3] + bj[3];
            if (RELU) {
                o.x = fmaxf(o.x, 0.f); o.y = fmaxf(o.y, 0.f);
                o.z = fmaxf(o.z, 0.f); o.w = fmaxf(o.w, 0.f);
            }
            *(float4*)(out + (size_t)row * HID + col_t * 4) = o;
        }
    }
}

// ---------------- ragged masked mean: one warp per row ----------------
__global__ void k_rowmean(const float* __restrict__ h, const int* __restrict__ ridx,
                          const unsigned char* __restrict__ rmask, float* __restrict__ outm) {
    long long gtid = (long long)blockIdx.x * blockDim.x + threadIdx.x;
    long long w = gtid >> 5;
    if (w >= NR) return;
    int lane = threadIdx.x & 31;
    const int is_int = g_mask_is_int;
    const int* rmask_i = (const int*)rmask;
    float4 acc = make_float4(0.f, 0.f, 0.f, 0.f);
    float cnt = 0.f;
#pragma unroll
    for (int f = 0; f < FF; f++) {
        bool on = is_int ? (__ldg(&rmask_i[w * FF + f]) != 0)
                         : (rmask[w * FF + f] != 0);
        if (on) {
            int idx = __ldg(&ridx[w * FF + f]);
            float4 v = __ldg((const float4*)(h + (size_t)idx * HID) + lane);
            acc.x += v.x; acc.y += v.y; acc.z += v.z; acc.w += v.w;
            cnt += 1.f;
        }
    }
    float inv = 1.f / fmaxf(cnt, 1.f);
    acc.x *= inv; acc.y *= inv; acc.z *= inv; acc.w *= inv;
    *((float4*)(outm + (size_t)w * HID) + lane) = acc;
}

// ---------------- final head: [NR][128] @ [128][10] + b ----------------
__global__ void k_head(const float* __restrict__ X, const float* __restrict__ W,
                       const float* __restrict__ b, float* __restrict__ out) {
    long long t = (long long)blockIdx.x * blockDim.x + threadIdx.x;
    int row = (int)(t >> 4);
    int c = (int)(t & 15);
    if (row >= NR || c >= NC) return;
    const float* x = X + (size_t)row * HID;
    float acc = b[c];
#pragma unroll
    for (int k = 0; k < HID; k++) acc += x[k] * __ldg(&W[k * NC + c]);
    out[(size_t)row * NC + c] = acc;
}

// ---------------- launch ----------------
extern "C" void kernel_launch(void* const* d_in, const int* in_sizes, int n_in,
                              void* d_out, int out_size) {
    const float* node_feats = (const float*)d_in[0];
    const int*   edges_src  = (const int*)  d_in[1];
    const int*   edges_dst  = (const int*)  d_in[2];
    const int*   row_idx    = (const int*)  d_in[3];
    const unsigned char* row_mask = (const unsigned char*)d_in[4];
    const float* W_in = (const float*)d_in[5];
    const float* b_in = (const float*)d_in[6];
    const float* W1   = (const float*)d_in[7];
    const float* b1   = (const float*)d_in[8];
    const float* W2   = (const float*)d_in[9];
    const float* b2   = (const float*)d_in[10];
    const float* Wm1  = (const float*)d_in[11];
    const float* bm1  = (const float*)d_in[12];
    const float* Wm2  = (const float*)d_in[13];
    const float* bm2  = (const float*)d_in[14];
    const float* Wm3  = (const float*)d_in[15];
    const float* bm3  = (const float*)d_in[16];
    float* out = (float*)d_out;

    float *p_h0, *p_h1, *p_h2, *p_agg, *p_dego, *p_degi, *p_mean, *p_x1, *p_x2;
    cudaGetSymbolAddress((void**)&p_h0,  g_h0);
    cudaGetSymbolAddress((void**)&p_h1,  g_h1);
    cudaGetSymbolAddress((void**)&p_h2,  g_h2);
    cudaGetSymbolAddress((void**)&p_agg, g_agg);
    cudaGetSymbolAddress((void**)&p_dego, g_deg_out);
    cudaGetSymbolAddress((void**)&p_degi, g_deg_in);
    cudaGetSymbolAddress((void**)&p_mean, g_mean);
    cudaGetSymbolAddress((void**)&p_x1,  g_x1);
    cudaGetSymbolAddress((void**)&p_x2,  g_x2);

    const long long agg4 = (long long)RR * NN * HID / 4;
    const long long deg4 = (long long)RR * NN / 4;

    // mask dtype detection
    k_detect_mask<<<1, 256>>>(row_mask);

    // degrees + norms
    k_zero4<<<2048, 256>>>((float4*)p_dego, deg4);
    k_zero4<<<2048, 256>>>((float4*)p_degi, deg4);
    k_deg<<<(RR * EE + 255) / 256, 256>>>(edges_src, edges_dst);
    k_norms<<<(RR * NN + 255) / 256, 256>>>();

    // input linear + relu
    k_gemm<true><<<(NN + 63) / 64, 256>>>(node_feats, W_in, b_in, p_h0, NN, IND);

    // RGCN layer 1
    k_zero4<<<8192, 256>>>((float4*)p_agg, agg4);
    {
        long long nt = (long long)RR * EE * 32;
        k_agg<<<(unsigned)((nt + 255) / 256), 256>>>(p_h0, edges_src, edges_dst);
    }
    k_layer_gemm<true><<<(NN + 63) / 64, 256>>>(W1, b1, p_h1);

    // RGCN layer 2
    k_zero4<<<8192, 256>>>((float4*)p_agg, agg4);
    {
        long long nt = (long long)RR * EE * 32;
        k_agg<<<(unsigned)((nt + 255) / 256), 256>>>(p_h1, edges_src, edges_dst);
    }
    k_layer_gemm<false><<<(NN + 63) / 64, 256>>>(W2, b2, p_h2);

    // ragged masked mean
    {
        long long nt = (long long)NR * 32;
        k_rowmean<<<(unsigned)((nt + 255) / 256), 256>>>(p_h2, row_idx, row_mask, p_mean);
    }

    // MLP head
    k_gemm<true><<<(NR + 63) / 64, 256>>>(p_mean, Wm1, bm1, p_x1, NR, HID);
    k_gemm<true><<<(NR + 63) / 64, 256>>>(p_x1,  Wm2, bm2, p_x2, NR, HID);
    k_head<<<(NR * 16 + 255) / 256, 256>>>(p_x2, Wm3, bm3, out);

    (void)in_sizes; (void)n_in; (void)out_size;
}